// round 1
// baseline (speedup 1.0000x reference)
#include <cuda_runtime.h>
#include <math.h>

#define NP 512
#define NB 512
#define NAT 32
#define NBT 40
#define NC 3
#define NTAB 40
#define NG 36
#define NA (NB*NAT)

__device__ __forceinline__ int wrapG(int v) {
    int m = v % NG;
    return (m < 0) ? m + NG : m;
}

__device__ __forceinline__ void cr_weights(float f, float w[4]) {
    float f2 = f * f;
    float f3 = f2 * f;
    w[0] = 0.5f * (-f3 + 2.0f * f2 - f);
    w[1] = 0.5f * (3.0f * f3 - 5.0f * f2 + 2.0f);
    w[2] = 0.5f * (-3.0f * f3 + 4.0f * f2 + f);
    w[3] = 0.5f * (f3 - f2);
}

__device__ __forceinline__ float dihedral(
    const float x[4], const float y[4], const float z[4])
{
    float b1x = x[1]-x[0], b1y = y[1]-y[0], b1z = z[1]-z[0];
    float b2x = x[2]-x[1], b2y = y[2]-y[1], b2z = z[2]-z[1];
    float b3x = x[3]-x[2], b3y = y[3]-y[2], b3z = z[3]-z[2];
    // n1 = b1 x b2
    float n1x = b1y*b2z - b1z*b2y;
    float n1y = b1z*b2x - b1x*b2z;
    float n1z = b1x*b2y - b1y*b2x;
    // n2 = b2 x b3
    float n2x = b2y*b3z - b2z*b3y;
    float n2y = b2z*b3x - b2x*b3z;
    float n2z = b2x*b3y - b2y*b3x;
    float b2n = sqrtf(b2x*b2x + b2y*b2y + b2z*b2z) + 1e-12f;
    float inv = 1.0f / b2n;
    float ux = b2x*inv, uy = b2y*inv, uz = b2z*inv;
    // m1 = n1 x u
    float m1x = n1y*uz - n1z*uy;
    float m1y = n1z*ux - n1x*uz;
    float m1z = n1x*uy - n1y*ux;
    float xx = n1x*n2x + n1y*n2y + n1z*n2z;
    float yy = m1x*n2x + m1y*n2y + m1z*n2z;
    return atan2f(yy, xx);
}

__global__ __launch_bounds__(NB) void rama_kernel(
    const float* __restrict__ coords,        // (P, NA, 3)
    const int*   __restrict__ offsets,       // (P, B)
    const int*   __restrict__ block_type,    // (P, B)
    const int*   __restrict__ inter,         // (P, B, NC, 2)
    const int*   __restrict__ down,          // (NBT, NC, NAT)
    const int*   __restrict__ bt_rama_table, // (NBT, 2)
    const int*   __restrict__ bt_upper,      // (NBT)
    const int*   __restrict__ bt_is_pro,     // (NBT)
    const int*   __restrict__ tor_atoms,     // (NBT, 8, 3)
    const float* __restrict__ tables,        // (NTAB, G, G)
    const float* __restrict__ tparams,       // (NTAB, 2, 2)
    float*       __restrict__ out)           // (P,)
{
    const int p  = blockIdx.x;
    const int b  = threadIdx.x;
    const int pb = p * NB + b;

    const int bt = block_type[pb];
    const int* offs_p   = offsets + p * NB;
    const int* bt_row   = block_type + p * NB;
    const int* inter_pb = inter + (size_t)pb * NC * 2;

    // Gather 8 torsion atoms
    float ax[8], ay[8], az[8];
    bool ok = true;
    #pragma unroll
    for (int t = 0; t < 8; t++) {
        const int base = (bt * 8 + t) * 3;
        const int ai = tor_atoms[base + 0];
        const int ci = tor_atoms[base + 1];
        const int nbonds = tor_atoms[base + 2];
        int gidx;
        bool aok;
        if (ai >= 0) {
            gidx = offs_p[b] + ai;
            aok = true;
        } else {
            const int sc = max(ci, 0);
            const int ob = inter_pb[sc * 2 + 0];
            const int oc = inter_pb[sc * 2 + 1];
            aok = (ci >= 0) && (ob >= 0);
            const int obc = min(max(ob, 0), NB - 1);
            const int occ = min(max(oc, 0), NC - 1);
            const int obt = bt_row[obc];
            const int da  = down[(obt * NC + occ) * NAT + nbonds];
            gidx = offs_p[obc] + da;
        }
        ok = ok && aok;
        gidx = min(max(gidx, 0), NA - 1);
        const float* c = coords + ((size_t)p * NA + gidx) * 3;
        ax[t] = c[0]; ay[t] = c[1]; az[t] = c[2];
    }

    // Two dihedrals
    float phi = dihedral(&ax[0], &ay[0], &az[0]);
    float psi = dihedral(&ax[4], &ay[4], &az[4]);

    // Table selection via upper connection neighbor
    const int uc = min(max(bt_upper[bt], 0), NC - 1);
    const int nbblk = inter_pb[uc * 2 + 0];
    const bool nb_ok = (nbblk >= 0);
    const int nbt = bt_row[min(max(nbblk, 0), NB - 1)];
    const int tab = bt_rama_table[bt * 2 + bt_is_pro[nbt]];

    const float start0 = tparams[tab * 4 + 0];
    const float start1 = tparams[tab * 4 + 1];
    const float step0  = tparams[tab * 4 + 2];
    const float step1  = tparams[tab * 4 + 3];

    const float u0 = (phi - start0) / step0;
    const float u1 = (psi - start1) / step1;
    const float i0f = floorf(u0);
    const float j0f = floorf(u1);
    const float f0 = u0 - i0f;
    const float f1 = u1 - j0f;
    const int i0 = (int)i0f;
    const int j0 = (int)j0f;

    float wp[4], wq[4];
    cr_weights(f0, wp);
    cr_weights(f1, wq);

    int ii[4], jj[4];
    #pragma unroll
    for (int k = 0; k < 4; k++) {
        ii[k] = wrapG(i0 - 1 + k);
        jj[k] = wrapG(j0 - 1 + k);
    }

    const float* tbl = tables + (size_t)tab * NG * NG;
    float e = 0.0f;
    #pragma unroll
    for (int i = 0; i < 4; i++) {
        const float* row = tbl + ii[i] * NG;
        float acc = 0.0f;
        #pragma unroll
        for (int j = 0; j < 4; j++) {
            acc += wq[j] * row[jj[j]];
        }
        e += wp[i] * acc;
    }

    const float contrib = (ok && nb_ok) ? e : 0.0f;

    // Block reduction over b (512 threads)
    __shared__ float sdata[NB];
    sdata[b] = contrib;
    __syncthreads();
    #pragma unroll
    for (int s = NB / 2; s > 0; s >>= 1) {
        if (b < s) sdata[b] += sdata[b + s];
        __syncthreads();
    }
    if (b == 0) out[p] = sdata[0];
}

extern "C" void kernel_launch(void* const* d_in, const int* in_sizes, int n_in,
                              void* d_out, int out_size) {
    const float* coords        = (const float*)d_in[0];
    const int*   offsets       = (const int*)d_in[1];
    const int*   block_type    = (const int*)d_in[2];
    const int*   inter         = (const int*)d_in[3];
    const int*   down          = (const int*)d_in[4];
    const int*   bt_rama_table = (const int*)d_in[5];
    const int*   bt_upper      = (const int*)d_in[6];
    const int*   bt_is_pro     = (const int*)d_in[7];
    const int*   tor_atoms     = (const int*)d_in[8];
    const float* tables        = (const float*)d_in[9];
    const float* tparams       = (const float*)d_in[10];
    float* out = (float*)d_out;

    rama_kernel<<<NP, NB>>>(coords, offsets, block_type, inter, down,
                            bt_rama_table, bt_upper, bt_is_pro, tor_atoms,
                            tables, tparams, out);
}

// round 2
// speedup vs baseline: 1.0008x; 1.0008x over previous
#include <cuda_runtime.h>
#include <math.h>

#define NP 512
#define NB 512
#define NAT 32
#define NBT 40
#define NC 3
#define NTAB 40
#define NG 36
#define NA (NB*NAT)

__device__ __forceinline__ int wrapG(int v) {
    int m = v % NG;
    return (m < 0) ? m + NG : m;
}

__device__ __forceinline__ void cr_weights(float f, float w[4]) {
    float f2 = f * f;
    float f3 = f2 * f;
    w[0] = 0.5f * (-f3 + 2.0f * f2 - f);
    w[1] = 0.5f * (3.0f * f3 - 5.0f * f2 + 2.0f);
    w[2] = 0.5f * (-3.0f * f3 + 4.0f * f2 + f);
    w[3] = 0.5f * (f3 - f2);
}

__device__ __forceinline__ float dihedral(
    const float x[4], const float y[4], const float z[4])
{
    float b1x = x[1]-x[0], b1y = y[1]-y[0], b1z = z[1]-z[0];
    float b2x = x[2]-x[1], b2y = y[2]-y[1], b2z = z[2]-z[1];
    float b3x = x[3]-x[2], b3y = y[3]-y[2], b3z = z[3]-z[2];
    float n1x = b1y*b2z - b1z*b2y;
    float n1y = b1z*b2x - b1x*b2z;
    float n1z = b1x*b2y - b1y*b2x;
    float n2x = b2y*b3z - b2z*b3y;
    float n2y = b2z*b3x - b2x*b3z;
    float n2z = b2x*b3y - b2y*b3x;
    float b2n = sqrtf(b2x*b2x + b2y*b2y + b2z*b2z) + 1e-12f;
    float inv = 1.0f / b2n;
    float ux = b2x*inv, uy = b2y*inv, uz = b2z*inv;
    float m1x = n1y*uz - n1z*uy;
    float m1y = n1z*ux - n1x*uz;
    float m1z = n1x*uy - n1y*ux;
    float xx = n1x*n2x + n1y*n2y + n1z*n2z;
    float yy = m1x*n2x + m1y*n2y + m1z*n2z;
    return atan2f(yy, xx);
}

__global__ __launch_bounds__(NB) void rama_kernel(
    const float* __restrict__ coords,        // (P, NA, 3)
    const int*   __restrict__ offsets,       // (P, B)
    const int*   __restrict__ block_type,    // (P, B)
    const int*   __restrict__ inter,         // (P, B, NC, 2)
    const int*   __restrict__ down,          // (NBT, NC, NAT)
    const int*   __restrict__ bt_rama_table, // (NBT, 2)
    const int*   __restrict__ bt_upper,      // (NBT)
    const int*   __restrict__ bt_is_pro,     // (NBT)
    const int*   __restrict__ tor_atoms,     // (NBT, 8, 3)
    const float* __restrict__ tables,        // (NTAB, G, G)
    const float* __restrict__ tparams,       // (NTAB, 2, 2)
    float*       __restrict__ out)           // (P,)
{
    __shared__ int   s_offs[NB];
    __shared__ int   s_bt[NB];
    __shared__ int   s_tor[NBT * 8 * 3];      // 960
    __shared__ int   s_down[NBT * NC * NAT];  // 3840
    __shared__ int   s_tabsel[NBT * 2];
    __shared__ int   s_upper[NBT];
    __shared__ int   s_ispro[NBT];
    __shared__ float s_tp[NTAB * 4];
    __shared__ float s_warp[16];

    const int p  = blockIdx.x;
    const int b  = threadIdx.x;
    const int pb = p * NB + b;

    // ---- stage metadata into shared (coalesced) ----
    s_offs[b] = offsets[pb];
    s_bt[b]   = block_type[pb];
    #pragma unroll
    for (int i = b; i < NBT * 8 * 3; i += NB) s_tor[i] = tor_atoms[i];
    #pragma unroll
    for (int i = b; i < NBT * NC * NAT; i += NB) s_down[i] = down[i];
    if (b < NBT * 2) s_tabsel[b] = bt_rama_table[b];
    if (b < NBT)     { s_upper[b] = bt_upper[b]; s_ispro[b] = bt_is_pro[b]; }
    if (b < NTAB*4)  s_tp[b] = tparams[b];

    // per-thread inter row into registers (independent of shared fill)
    const int* inter_pb = inter + (size_t)pb * NC * 2;
    const int iv0 = inter_pb[0], iv1 = inter_pb[1];
    const int iv2 = inter_pb[2], iv3 = inter_pb[3];
    const int iv4 = inter_pb[4], iv5 = inter_pb[5];

    __syncthreads();

    const int bt   = s_bt[b];
    const int offb = s_offs[b];

    // ---- compute all 8 gather indices from shared ----
    int  gidx[8];
    bool ok = true;
    #pragma unroll
    for (int t = 0; t < 8; t++) {
        const int base = (bt * 8 + t) * 3;
        const int ai     = s_tor[base + 0];
        const int ci     = s_tor[base + 1];
        const int nbonds = s_tor[base + 2];
        int g;
        bool aok;
        if (ai >= 0) {
            g = offb + ai;
            aok = true;
        } else {
            const int sc = max(ci, 0);
            const int ob = (sc == 0) ? iv0 : ((sc == 1) ? iv2 : iv4);
            const int oc = (sc == 0) ? iv1 : ((sc == 1) ? iv3 : iv5);
            aok = (ci >= 0) && (ob >= 0);
            const int obc = min(max(ob, 0), NB - 1);
            const int occ = min(max(oc, 0), NC - 1);
            const int obt = s_bt[obc];
            const int da  = s_down[(obt * NC + occ) * NAT + nbonds];
            g = s_offs[obc] + da;
        }
        ok = ok && aok;
        gidx[t] = min(max(g, 0), NA - 1);
    }

    // ---- issue all coord loads back-to-back (max MLP) ----
    float ax[8], ay[8], az[8];
    const float* cp = coords + (size_t)p * NA * 3;
    #pragma unroll
    for (int t = 0; t < 8; t++) {
        const float* c = cp + (size_t)gidx[t] * 3;
        ax[t] = __ldg(c + 0);
        ay[t] = __ldg(c + 1);
        az[t] = __ldg(c + 2);
    }

    const float phi = dihedral(&ax[0], &ay[0], &az[0]);
    const float psi = dihedral(&ax[4], &ay[4], &az[4]);

    // ---- table selection (all shared) ----
    const int uc    = min(max(s_upper[bt], 0), NC - 1);
    const int nbblk = (uc == 0) ? iv0 : ((uc == 1) ? iv2 : iv4);
    const bool nb_ok = (nbblk >= 0);
    const int nbt = s_bt[min(max(nbblk, 0), NB - 1)];
    const int tab = s_tabsel[bt * 2 + s_ispro[nbt]];

    const float start0 = s_tp[tab * 4 + 0];
    const float start1 = s_tp[tab * 4 + 1];
    const float step0  = s_tp[tab * 4 + 2];
    const float step1  = s_tp[tab * 4 + 3];

    const float u0 = (phi - start0) / step0;
    const float u1 = (psi - start1) / step1;
    const float i0f = floorf(u0);
    const float j0f = floorf(u1);
    const float f0 = u0 - i0f;
    const float f1 = u1 - j0f;
    const int i0 = (int)i0f;
    const int j0 = (int)j0f;

    float wp[4], wq[4];
    cr_weights(f0, wp);
    cr_weights(f1, wq);

    int ii[4], jj[4];
    #pragma unroll
    for (int k = 0; k < 4; k++) {
        ii[k] = wrapG(i0 - 1 + k);
        jj[k] = wrapG(j0 - 1 + k);
    }

    const float* tbl = tables + (size_t)tab * NG * NG;
    // issue all 16 table loads with MLP, then combine
    float tv[4][4];
    #pragma unroll
    for (int i = 0; i < 4; i++) {
        const float* row = tbl + ii[i] * NG;
        #pragma unroll
        for (int j = 0; j < 4; j++) tv[i][j] = __ldg(row + jj[j]);
    }
    float e = 0.0f;
    #pragma unroll
    for (int i = 0; i < 4; i++) {
        float acc = 0.0f;
        #pragma unroll
        for (int j = 0; j < 4; j++) acc = fmaf(wq[j], tv[i][j], acc);
        e = fmaf(wp[i], acc, e);
    }

    float v = (ok && nb_ok) ? e : 0.0f;

    // ---- warp-shuffle reduction ----
    const int lane = b & 31;
    const int wid  = b >> 5;
    #pragma unroll
    for (int o = 16; o > 0; o >>= 1)
        v += __shfl_down_sync(0xffffffffu, v, o);
    if (lane == 0) s_warp[wid] = v;
    __syncthreads();
    if (wid == 0) {
        float x = (lane < 16) ? s_warp[lane] : 0.0f;
        #pragma unroll
        for (int o = 8; o > 0; o >>= 1)
            x += __shfl_down_sync(0xffffffffu, x, o);
        if (lane == 0) out[p] = x;
    }
}

extern "C" void kernel_launch(void* const* d_in, const int* in_sizes, int n_in,
                              void* d_out, int out_size) {
    const float* coords        = (const float*)d_in[0];
    const int*   offsets       = (const int*)d_in[1];
    const int*   block_type    = (const int*)d_in[2];
    const int*   inter         = (const int*)d_in[3];
    const int*   down          = (const int*)d_in[4];
    const int*   bt_rama_table = (const int*)d_in[5];
    const int*   bt_upper      = (const int*)d_in[6];
    const int*   bt_is_pro     = (const int*)d_in[7];
    const int*   tor_atoms     = (const int*)d_in[8];
    const float* tables        = (const float*)d_in[9];
    const float* tparams       = (const float*)d_in[10];
    float* out = (float*)d_out;

    rama_kernel<<<NP, NB>>>(coords, offsets, block_type, inter, down,
                            bt_rama_table, bt_upper, bt_is_pro, tor_atoms,
                            tables, tparams, out);
}

// round 3
// speedup vs baseline: 1.4409x; 1.4398x over previous
#include <cuda_runtime.h>
#include <math.h>

#define NP 512
#define NB 512
#define NAT 32
#define NBT 40
#define NC 3
#define NTAB 40
#define NG 36
#define NA (NB*NAT)

__device__ __forceinline__ int wrapG(int v) {
    int m = v % NG;
    return (m < 0) ? m + NG : m;
}

__device__ __forceinline__ void cr_weights(float f, float w[4]) {
    float f2 = f * f;
    float f3 = f2 * f;
    w[0] = 0.5f * (-f3 + 2.0f * f2 - f);
    w[1] = 0.5f * (3.0f * f3 - 5.0f * f2 + 2.0f);
    w[2] = 0.5f * (-3.0f * f3 + 4.0f * f2 + f);
    w[3] = 0.5f * (f3 - f2);
}

__device__ __forceinline__ float dihedral(
    const float x[4], const float y[4], const float z[4])
{
    float b1x = x[1]-x[0], b1y = y[1]-y[0], b1z = z[1]-z[0];
    float b2x = x[2]-x[1], b2y = y[2]-y[1], b2z = z[2]-z[1];
    float b3x = x[3]-x[2], b3y = y[3]-y[2], b3z = z[3]-z[2];
    float n1x = b1y*b2z - b1z*b2y;
    float n1y = b1z*b2x - b1x*b2z;
    float n1z = b1x*b2y - b1y*b2x;
    float n2x = b2y*b3z - b2z*b3y;
    float n2y = b2z*b3x - b2x*b3z;
    float n2z = b2x*b3y - b2y*b3x;
    float b2n = sqrtf(b2x*b2x + b2y*b2y + b2z*b2z) + 1e-12f;
    float inv = 1.0f / b2n;
    float ux = b2x*inv, uy = b2y*inv, uz = b2z*inv;
    float m1x = n1y*uz - n1z*uy;
    float m1y = n1z*ux - n1x*uz;
    float m1z = n1x*uy - n1y*ux;
    float xx = n1x*n2x + n1y*n2y + n1z*n2z;
    float yy = m1x*n2x + m1y*n2y + m1z*n2z;
    return atan2f(yy, xx);
}

__global__ __launch_bounds__(NB) void rama_kernel(
    const float* __restrict__ coords,        // (P, NA, 3)
    const int*   __restrict__ offsets,       // (P, B)
    const int*   __restrict__ block_type,    // (P, B)
    const int*   __restrict__ inter,         // (P, B, NC, 2)
    const int*   __restrict__ down,          // (NBT, NC, NAT)
    const int*   __restrict__ bt_rama_table, // (NBT, 2)
    const int*   __restrict__ bt_upper,      // (NBT)
    const int*   __restrict__ bt_is_pro,     // (NBT)
    const int*   __restrict__ tor_atoms,     // (NBT, 8, 3)
    const float* __restrict__ tables,        // (NTAB, G, G)
    const float* __restrict__ tparams,       // (NTAB, 2, 2)
    float*       __restrict__ out)           // (P,)
{
    __shared__ int   s_offs[NB];
    __shared__ int   s_bt[NB];
    __shared__ alignas(16) int   s_tor[NBT * 8 * 3];      // 960 ints
    __shared__ alignas(16) int   s_down[NBT * NC * NAT];  // 3840 ints
    __shared__ int   s_tabsel[NBT * 2];
    __shared__ int   s_upper[NBT];
    __shared__ int   s_ispro[NBT];
    __shared__ float s_tp[NTAB * 4];
    __shared__ float s_warp[16];

    const int p  = blockIdx.x;
    const int b  = threadIdx.x;
    const int pb = p * NB + b;

    // ---- stage metadata into shared (vectorized, coalesced) ----
    s_offs[b] = offsets[pb];
    s_bt[b]   = block_type[pb];
    {
        const int4* g4 = (const int4*)down;   // 960 int4
        int4* s4 = (int4*)s_down;
        #pragma unroll
        for (int i = b; i < 960; i += NB) s4[i] = g4[i];
        const int4* t4 = (const int4*)tor_atoms; // 240 int4
        int4* st4 = (int4*)s_tor;
        if (b < 240) st4[b] = t4[b];
    }
    if (b < NBT * 2) s_tabsel[b] = bt_rama_table[b];
    if (b < NBT)     { s_upper[b] = bt_upper[b]; s_ispro[b] = bt_is_pro[b]; }
    if (b < NTAB*4)  s_tp[b] = tparams[b];

    // per-thread inter row: 24 bytes, 8-aligned -> 3x int2
    const int2* ip2 = (const int2*)(inter + (size_t)pb * 6);
    const int2 ia = ip2[0], ib2 = ip2[1], ic = ip2[2];
    const int iv0 = ia.x,  iv1 = ia.y;
    const int iv2 = ib2.x, iv3 = ib2.y;
    const int iv4 = ic.x,  iv5 = ic.y;

    __syncthreads();

    const int bt   = s_bt[b];
    const int offb = s_offs[b];

    // ---- compute all 8 gather indices from shared ----
    int  gidx[8];
    bool ok = true;
    #pragma unroll
    for (int t = 0; t < 8; t++) {
        const int base = (bt * 8 + t) * 3;
        const int ai     = s_tor[base + 0];
        const int ci     = s_tor[base + 1];
        const int nbonds = s_tor[base + 2];
        int g;
        bool aok;
        if (ai >= 0) {
            g = offb + ai;
            aok = true;
        } else {
            const int sc = max(ci, 0);
            const int ob = (sc == 0) ? iv0 : ((sc == 1) ? iv2 : iv4);
            const int oc = (sc == 0) ? iv1 : ((sc == 1) ? iv3 : iv5);
            aok = (ci >= 0) && (ob >= 0);
            const int obc = min(max(ob, 0), NB - 1);
            const int occ = min(max(oc, 0), NC - 1);
            const int obt = s_bt[obc];
            const int da  = s_down[(obt * NC + occ) * NAT + nbonds];
            g = s_offs[obc] + da;
        }
        ok = ok && aok;
        gidx[t] = min(max(g, 0), NA - 1);
    }

    // ---- coord gather: 2x float2 per atom (parity select), dedup psi vs phi ----
    float ax[8], ay[8], az[8];
    const float2* cp2 = (const float2*)(coords + (size_t)p * NA * 3);
    #pragma unroll
    for (int t = 0; t < 8; t++) {
        const bool dup = (t >= 4 && t <= 6) && (gidx[t] == gidx[t-3]);
        if (dup) {
            ax[t] = ax[t-3]; ay[t] = ay[t-3]; az[t] = az[t-3];
        } else {
            const int base = gidx[t] * 3;       // float index
            const int h = base >> 1;            // float2 index
            const float2 A = __ldg(cp2 + h);
            const float2 B = __ldg(cp2 + h + 1);
            const bool even = (base & 1) == 0;
            ax[t] = even ? A.x : A.y;
            ay[t] = even ? A.y : B.x;
            az[t] = even ? B.x : B.y;
        }
    }

    const float phi = dihedral(&ax[0], &ay[0], &az[0]);
    const float psi = dihedral(&ax[4], &ay[4], &az[4]);

    // ---- table selection (all shared) ----
    const int uc    = min(max(s_upper[bt], 0), NC - 1);
    const int nbblk = (uc == 0) ? iv0 : ((uc == 1) ? iv2 : iv4);
    const bool nb_ok = (nbblk >= 0);
    const int nbt = s_bt[min(max(nbblk, 0), NB - 1)];
    const int tab = s_tabsel[bt * 2 + s_ispro[nbt]];

    const float start0 = s_tp[tab * 4 + 0];
    const float start1 = s_tp[tab * 4 + 1];
    const float step0  = s_tp[tab * 4 + 2];
    const float step1  = s_tp[tab * 4 + 3];

    const float u0 = (phi - start0) / step0;
    const float u1 = (psi - start1) / step1;
    const float i0f = floorf(u0);
    const float j0f = floorf(u1);
    const float f0 = u0 - i0f;
    const float f1 = u1 - j0f;
    const int i0 = (int)i0f;
    const int j0 = (int)j0f;

    float wp[4], wq[4];
    cr_weights(f0, wp);
    cr_weights(f1, wq);

    int ii[4], jj[4];
    #pragma unroll
    for (int k = 0; k < 4; k++) {
        ii[k] = wrapG(i0 - 1 + k);
        jj[k] = wrapG(j0 - 1 + k);
    }

    const float* tbl = tables + (size_t)tab * NG * NG;
    float tv[4][4];
    #pragma unroll
    for (int i = 0; i < 4; i++) {
        const float* row = tbl + ii[i] * NG;
        #pragma unroll
        for (int j = 0; j < 4; j++) tv[i][j] = __ldg(row + jj[j]);
    }
    float e = 0.0f;
    #pragma unroll
    for (int i = 0; i < 4; i++) {
        float acc = 0.0f;
        #pragma unroll
        for (int j = 0; j < 4; j++) acc = fmaf(wq[j], tv[i][j], acc);
        e = fmaf(wp[i], acc, e);
    }

    float v = (ok && nb_ok) ? e : 0.0f;

    // ---- warp-shuffle reduction ----
    const int lane = b & 31;
    const int wid  = b >> 5;
    #pragma unroll
    for (int o = 16; o > 0; o >>= 1)
        v += __shfl_down_sync(0xffffffffu, v, o);
    if (lane == 0) s_warp[wid] = v;
    __syncthreads();
    if (wid == 0) {
        float x = (lane < 16) ? s_warp[lane] : 0.0f;
        #pragma unroll
        for (int o = 8; o > 0; o >>= 1)
            x += __shfl_down_sync(0xffffffffu, x, o);
        if (lane == 0) out[p] = x;
    }
}

extern "C" void kernel_launch(void* const* d_in, const int* in_sizes, int n_in,
                              void* d_out, int out_size) {
    const float* coords        = (const float*)d_in[0];
    const int*   offsets       = (const int*)d_in[1];
    const int*   block_type    = (const int*)d_in[2];
    const int*   inter         = (const int*)d_in[3];
    const int*   down          = (const int*)d_in[4];
    const int*   bt_rama_table = (const int*)d_in[5];
    const int*   bt_upper      = (const int*)d_in[6];
    const int*   bt_is_pro     = (const int*)d_in[7];
    const int*   tor_atoms     = (const int*)d_in[8];
    const float* tables        = (const float*)d_in[9];
    const float* tparams       = (const float*)d_in[10];
    float* out = (float*)d_out;

    rama_kernel<<<NP, NB>>>(coords, offsets, block_type, inter, down,
                            bt_rama_table, bt_upper, bt_is_pro, tor_atoms,
                            tables, tparams, out);
}

// round 4
// speedup vs baseline: 1.4632x; 1.0154x over previous
#include <cuda_runtime.h>
#include <math.h>

#define NP 512
#define NB 512
#define NAT 32
#define NBT 40
#define NC 3
#define NTAB 40
#define NG 36
#define NA (NB*NAT)

// Repacked tables: for each (tab,row,c0), the 4 wrapped column taps as one float4.
__device__ float4 g_tbl4[NTAB * NG * NG];

__global__ void repack_tables_kernel(const float* __restrict__ tables) {
    const int idx = blockIdx.x * blockDim.x + threadIdx.x;
    if (idx >= NTAB * NG * NG) return;
    const int c0 = idx % NG;
    const float* row = tables + (idx / NG) * NG;  // idx = (tab*NG + i)*NG + c0
    int c1 = c0 + 1; if (c1 >= NG) c1 -= NG;
    int c2 = c0 + 2; if (c2 >= NG) c2 -= NG;
    int c3 = c0 + 3; if (c3 >= NG) c3 -= NG;
    g_tbl4[idx] = make_float4(row[c0], row[c1], row[c2], row[c3]);
}

__device__ __forceinline__ int wrapG(int v) {
    int m = v % NG;
    return (m < 0) ? m + NG : m;
}

__device__ __forceinline__ void cr_weights(float f, float w[4]) {
    float f2 = f * f;
    float f3 = f2 * f;
    w[0] = 0.5f * (-f3 + 2.0f * f2 - f);
    w[1] = 0.5f * (3.0f * f3 - 5.0f * f2 + 2.0f);
    w[2] = 0.5f * (-3.0f * f3 + 4.0f * f2 + f);
    w[3] = 0.5f * (f3 - f2);
}

__device__ __forceinline__ float dihedral(
    const float x[4], const float y[4], const float z[4])
{
    float b1x = x[1]-x[0], b1y = y[1]-y[0], b1z = z[1]-z[0];
    float b2x = x[2]-x[1], b2y = y[2]-y[1], b2z = z[2]-z[1];
    float b3x = x[3]-x[2], b3y = y[3]-y[2], b3z = z[3]-z[2];
    float n1x = b1y*b2z - b1z*b2y;
    float n1y = b1z*b2x - b1x*b2z;
    float n1z = b1x*b2y - b1y*b2x;
    float n2x = b2y*b3z - b2z*b3y;
    float n2y = b2z*b3x - b2x*b3z;
    float n2z = b2x*b3y - b2y*b3x;
    float b2n = sqrtf(b2x*b2x + b2y*b2y + b2z*b2z) + 1e-12f;
    float inv = 1.0f / b2n;
    float ux = b2x*inv, uy = b2y*inv, uz = b2z*inv;
    float m1x = n1y*uz - n1z*uy;
    float m1y = n1z*ux - n1x*uz;
    float m1z = n1x*uy - n1y*ux;
    float xx = n1x*n2x + n1y*n2y + n1z*n2z;
    float yy = m1x*n2x + m1y*n2y + m1z*n2z;
    return atan2f(yy, xx);
}

// Load one xyz triple with 1 aligned LDG.128 + (predicated) 1 LDG.64 spill.
__device__ __forceinline__ void load_xyz(
    const float4* __restrict__ cp4, const float2* __restrict__ cp2,
    int gidx, float& x, float& y, float& z)
{
    const int base = gidx * 3;
    const int r = base & 3;
    const float4 V = __ldg(cp4 + (base >> 2));
    if (r <= 1) {
        x = r ? V.y : V.x;
        y = r ? V.z : V.y;
        z = r ? V.w : V.z;
    } else {
        const int h2 = (base + 1 + (r == 2 ? 1 : 0)) >> 1;
        const float2 E = __ldg(cp2 + h2);
        if (r == 2) { x = V.z; y = V.w; z = E.x; }
        else        { x = V.w; y = E.x; z = E.y; }
    }
}

__global__ __launch_bounds__(NB) void rama_kernel(
    const float* __restrict__ coords,        // (P, NA, 3)
    const int*   __restrict__ offsets,       // (P, B)
    const int*   __restrict__ block_type,    // (P, B)
    const int*   __restrict__ inter,         // (P, B, NC, 2)
    const int*   __restrict__ down,          // (NBT, NC, NAT)
    const int*   __restrict__ bt_rama_table, // (NBT, 2)
    const int*   __restrict__ bt_upper,      // (NBT)
    const int*   __restrict__ bt_is_pro,     // (NBT)
    const int*   __restrict__ tor_atoms,     // (NBT, 8, 3)
    const float* __restrict__ tparams,       // (NTAB, 2, 2)
    float*       __restrict__ out)           // (P,)
{
    __shared__ int   s_offs[NB];
    __shared__ int   s_bt[NB];
    __shared__ alignas(16) int   s_tor[NBT * 8 * 3];
    __shared__ alignas(16) int   s_down[NBT * NC * NAT];
    __shared__ int   s_tabsel[NBT * 2];
    __shared__ int   s_upper[NBT];
    __shared__ int   s_ispro[NBT];
    __shared__ float s_tp[NTAB * 4];
    __shared__ float s_warp[16];

    const int p  = blockIdx.x;
    const int b  = threadIdx.x;
    const int pb = p * NB + b;

    s_offs[b] = offsets[pb];
    s_bt[b]   = block_type[pb];
    {
        const int4* g4 = (const int4*)down;   // 960 int4
        int4* s4 = (int4*)s_down;
        #pragma unroll
        for (int i = b; i < 960; i += NB) s4[i] = g4[i];
        const int4* t4 = (const int4*)tor_atoms; // 240 int4
        int4* st4 = (int4*)s_tor;
        if (b < 240) st4[b] = t4[b];
    }
    if (b < NBT * 2) s_tabsel[b] = bt_rama_table[b];
    if (b < NBT)     { s_upper[b] = bt_upper[b]; s_ispro[b] = bt_is_pro[b]; }
    if (b < NTAB*4)  s_tp[b] = tparams[b];

    const int2* ip2 = (const int2*)(inter + (size_t)pb * 6);
    const int2 ia = ip2[0], ib2 = ip2[1], ic = ip2[2];
    const int iv0 = ia.x,  iv1 = ia.y;
    const int iv2 = ib2.x, iv3 = ib2.y;
    const int iv4 = ic.x,  iv5 = ic.y;

    __syncthreads();

    const int bt   = s_bt[b];
    const int offb = s_offs[b];

    int  gidx[8];
    bool ok = true;
    #pragma unroll
    for (int t = 0; t < 8; t++) {
        const int base = (bt * 8 + t) * 3;
        const int ai     = s_tor[base + 0];
        const int ci     = s_tor[base + 1];
        const int nbonds = s_tor[base + 2];
        int g;
        bool aok;
        if (ai >= 0) {
            g = offb + ai;
            aok = true;
        } else {
            const int sc = max(ci, 0);
            const int ob = (sc == 0) ? iv0 : ((sc == 1) ? iv2 : iv4);
            const int oc = (sc == 0) ? iv1 : ((sc == 1) ? iv3 : iv5);
            aok = (ci >= 0) && (ob >= 0);
            const int obc = min(max(ob, 0), NB - 1);
            const int occ = min(max(oc, 0), NC - 1);
            const int obt = s_bt[obc];
            const int da  = s_down[(obt * NC + occ) * NAT + nbonds];
            g = s_offs[obc] + da;
        }
        ok = ok && aok;
        gidx[t] = min(max(g, 0), NA - 1);
    }

    float ax[8], ay[8], az[8];
    const float4* cp4 = (const float4*)(coords + (size_t)p * NA * 3);
    const float2* cp2 = (const float2*)(coords + (size_t)p * NA * 3);
    #pragma unroll
    for (int t = 0; t < 8; t++) {
        const bool dup = (t >= 4 && t <= 6) && (gidx[t] == gidx[t-3]);
        if (dup) {
            ax[t] = ax[t-3]; ay[t] = ay[t-3]; az[t] = az[t-3];
        } else {
            load_xyz(cp4, cp2, gidx[t], ax[t], ay[t], az[t]);
        }
    }

    const float phi = dihedral(&ax[0], &ay[0], &az[0]);
    const float psi = dihedral(&ax[4], &ay[4], &az[4]);

    const int uc    = min(max(s_upper[bt], 0), NC - 1);
    const int nbblk = (uc == 0) ? iv0 : ((uc == 1) ? iv2 : iv4);
    const bool nb_ok = (nbblk >= 0);
    const int nbt = s_bt[min(max(nbblk, 0), NB - 1)];
    const int tab = s_tabsel[bt * 2 + s_ispro[nbt]];

    const float start0 = s_tp[tab * 4 + 0];
    const float start1 = s_tp[tab * 4 + 1];
    const float step0  = s_tp[tab * 4 + 2];
    const float step1  = s_tp[tab * 4 + 3];

    const float u0 = (phi - start0) / step0;
    const float u1 = (psi - start1) / step1;
    const float i0f = floorf(u0);
    const float j0f = floorf(u1);
    const float f0 = u0 - i0f;
    const float f1 = u1 - j0f;
    const int i0 = (int)i0f;
    const int j0 = (int)j0f;

    float wp[4], wq[4];
    cr_weights(f0, wp);
    cr_weights(f1, wq);

    const int c0 = wrapG(j0 - 1);
    const int tabbase = tab * NG * NG;

    // 4 rows, each one aligned float4 from the repacked table.
    float4 tv[4];
    #pragma unroll
    for (int i = 0; i < 4; i++) {
        const int ri = wrapG(i0 - 1 + i);
        tv[i] = __ldg(&g_tbl4[tabbase + ri * NG + c0]);
    }

    float e = 0.0f;
    #pragma unroll
    for (int i = 0; i < 4; i++) {
        float acc;
        acc = wq[0] * tv[i].x;
        acc = fmaf(wq[1], tv[i].y, acc);
        acc = fmaf(wq[2], tv[i].z, acc);
        acc = fmaf(wq[3], tv[i].w, acc);
        e = fmaf(wp[i], acc, e);
    }

    float v = (ok && nb_ok) ? e : 0.0f;

    const int lane = b & 31;
    const int wid  = b >> 5;
    #pragma unroll
    for (int o = 16; o > 0; o >>= 1)
        v += __shfl_down_sync(0xffffffffu, v, o);
    if (lane == 0) s_warp[wid] = v;
    __syncthreads();
    if (wid == 0) {
        float x = (lane < 16) ? s_warp[lane] : 0.0f;
        #pragma unroll
        for (int o = 8; o > 0; o >>= 1)
            x += __shfl_down_sync(0xffffffffu, x, o);
        if (lane == 0) out[p] = x;
    }
}

extern "C" void kernel_launch(void* const* d_in, const int* in_sizes, int n_in,
                              void* d_out, int out_size) {
    const float* coords        = (const float*)d_in[0];
    const int*   offsets       = (const int*)d_in[1];
    const int*   block_type    = (const int*)d_in[2];
    const int*   inter         = (const int*)d_in[3];
    const int*   down          = (const int*)d_in[4];
    const int*   bt_rama_table = (const int*)d_in[5];
    const int*   bt_upper      = (const int*)d_in[6];
    const int*   bt_is_pro     = (const int*)d_in[7];
    const int*   tor_atoms     = (const int*)d_in[8];
    const float* tables        = (const float*)d_in[9];
    const float* tparams       = (const float*)d_in[10];
    float* out = (float*)d_out;

    const int ntab_elems = NTAB * NG * NG;
    repack_tables_kernel<<<(ntab_elems + 255) / 256, 256>>>(tables);
    rama_kernel<<<NP, NB>>>(coords, offsets, block_type, inter, down,
                            bt_rama_table, bt_upper, bt_is_pro, tor_atoms,
                            tparams, out);
}